// round 11
// baseline (speedup 1.0000x reference)
#include <cuda_runtime.h>
#include <cuda_fp16.h>
#include <cstdint>

// ---------------------------------------------------------------------------
// Problem constants
// ---------------------------------------------------------------------------
namespace {
constexpr int T_STEPS = 128, BATCH = 512, HID = 512, INP = 512;
constexpr long long BH = (long long)BATCH * HID;    // 262144 sequences

// Fused kernel tiling: CTA = (all 128 t) x (256 h), BK=16, warp tile 64x64
constexpr int BM = 128, BN = 256, BK = 16;
constexpr int CHUNKS = INP / BK;                    // 32
constexpr int PITCH  = 48;                          // 32B data + 16B pad (bank-clean)
constexpr int A_T    = BM * PITCH;                  // 6144  per A split
constexpr int B_T    = BN * PITCH;                  // 12288 per B split
// W cp.async pipeline: 4 stages x (Bh, Bm)
constexpr int WSTAGE_B = 2 * B_T;                   // 24576
constexpr int NWSTAGE  = 4;
constexpr int W_PIPE_B = NWSTAGE * WSTAGE_B;        // 98304
// A ping-pong buffers (LDG fp32 -> cvt -> STS): 2 bufs x (Ah, Am)
constexpr int A_BASE  = W_PIPE_B;                   // 98304
constexpr int A_BUF_B = 2 * A_T;                    // 12288 per buf
// xp fp32 tile overlays everything after the mainloop: 128 x 256, pitch 264
constexpr int XP = 264;
constexpr int XP_BYTES = 128 * XP * 4;              // 135168
constexpr int SMEM_TOTAL = XP_BYTES;                // > 98304 + 24576 = 122880
// W split launch: HID*INP/4 float4, 8 per thread, 256 threads/block
constexpr int W_F4      = HID * INP / 4;            // 65536
constexpr int W_SPLIT_BLOCKS = W_F4 / 8 / 256;      // 32  (R10 bug: was 128)
}

// Static scratch (allowed; no allocs) — W splits only
__device__ __half g_wh[(size_t)HID * INP];          // [H][K]
__device__ __half g_wm[(size_t)HID * INP];

// ---------------------------------------------------------------------------
// PTX helpers
// ---------------------------------------------------------------------------
__device__ __forceinline__ uint32_t smem_u32(const void* p) {
    uint32_t a;
    asm("{ .reg .u64 t; cvta.to.shared.u64 t, %1; cvt.u32.u64 %0, t; }"
        : "=r"(a) : "l"(p));
    return a;
}
__device__ __forceinline__ void ldsm_x4(uint32_t* r, uint32_t addr) {
    asm volatile("ldmatrix.sync.aligned.m8n8.x4.shared.b16 {%0,%1,%2,%3}, [%4];"
                 : "=r"(r[0]), "=r"(r[1]), "=r"(r[2]), "=r"(r[3]) : "r"(addr));
}
__device__ __forceinline__ void mma_f16(float* c, const uint32_t* a,
                                        const uint32_t* b) {
    asm volatile(
        "mma.sync.aligned.m16n8k16.row.col.f32.f16.f16.f32 "
        "{%0,%1,%2,%3}, {%4,%5,%6,%7}, {%8,%9}, {%0,%1,%2,%3};"
        : "+f"(c[0]), "+f"(c[1]), "+f"(c[2]), "+f"(c[3])
        : "r"(a[0]), "r"(a[1]), "r"(a[2]), "r"(a[3]), "r"(b[0]), "r"(b[1]));
}
__device__ __forceinline__ void cp16(uint32_t dst, const void* src) {
    asm volatile("cp.async.cg.shared.global [%0], [%1], 16;"
                 :: "r"(dst), "l"(src) : "memory");
}
__device__ __forceinline__ void cp_commit() {
    asm volatile("cp.async.commit_group;" ::: "memory");
}
__device__ __forceinline__ void cp_wait2() {
    asm volatile("cp.async.wait_group 2;" ::: "memory");
}
__device__ __forceinline__ uint32_t hpack(__half a, __half b) {
    __half2 t(a, b);
    return *reinterpret_cast<uint32_t*>(&t);
}

// ---------------------------------------------------------------------------
// W split: fp32 [H,K] -> (hi, mid) fp16.  8 float4 per thread, 32 blocks.
// ---------------------------------------------------------------------------
__global__ __launch_bounds__(256)
void split_w_kernel(const float4* __restrict__ W)
{
    const int i = (blockIdx.x * 256 + threadIdx.x) * 8;   // < W_F4
    float4 v[8];
    #pragma unroll
    for (int g = 0; g < 8; ++g) v[g] = W[i + g];
    uint32_t hp[16], mp[16];
    #pragma unroll
    for (int g = 0; g < 8; ++g) {
        const float f[4] = {v[g].x, v[g].y, v[g].z, v[g].w};
        __half h[4], m[4];
        #pragma unroll
        for (int j = 0; j < 4; ++j) {
            h[j] = __float2half_rn(f[j]);
            m[j] = __float2half_rn(f[j] - __half2float(h[j]));
        }
        hp[g * 2 + 0] = hpack(h[0], h[1]); hp[g * 2 + 1] = hpack(h[2], h[3]);
        mp[g * 2 + 0] = hpack(m[0], m[1]); mp[g * 2 + 1] = hpack(m[2], m[3]);
    }
    uint4* hd = (uint4*)g_wh;
    uint4* md = (uint4*)g_wm;
    const int o = i / 2;
    #pragma unroll
    for (int g = 0; g < 4; ++g) {
        hd[o + g] = make_uint4(hp[4 * g], hp[4 * g + 1], hp[4 * g + 2], hp[4 * g + 3]);
        md[o + g] = make_uint4(mp[4 * g], mp[4 * g + 1], mp[4 * g + 2], mp[4 * g + 3]);
    }
}

// ---------------------------------------------------------------------------
// FUSED kernel, CTA = (hblk of 256, batch b):
//   A path: LDG x fp32 -> in-register hi/mid fp16 split -> STS (2-buf ping-pong)
//   B path: pre-split W via 4-stage cp.async
//   GEMM: 3 fp16 HMMA terms hh+hm+mh; then smem xp tile; then in-CTA LIF scan.
// ---------------------------------------------------------------------------
__global__ __launch_bounds__(256, 1)
void fused_kernel(const float* __restrict__ x, const float* __restrict__ bias,
                  float* __restrict__ out, float* __restrict__ states)
{
    extern __shared__ char smem[];
    const uint32_t sbase = smem_u32(smem);
    const int tid = threadIdx.x;
    const int wid = tid >> 5;
    const int lid = tid & 31;
    const int n0 = blockIdx.x * BN;                  // h block (0 or 256)
    const int b  = blockIdx.y;                       // batch

    const int warp_m = wid & 1;          // 64-row (t) half
    const int warp_n = wid >> 1;         // 64-col (h) slice

    const int quad = lid >> 3, lrow = lid & 7;
    const uint32_t laneA = (uint32_t)(((quad & 1) * 8 + lrow) * PITCH + (quad >> 1) * 16);
    const uint32_t laneB = (uint32_t)(((quad >> 1) * 8 + lrow) * PITCH + (quad & 1) * 16);

    // A staging coords: thread -> (row = tid>>1, 8-col group cc = tid&1)
    const int arow = tid >> 1;
    const int acc8 = (tid & 1) * 8;
    const float* axbase = x + ((size_t)arow * BATCH + b) * INP + acc8;
    const uint32_t asts  = (uint32_t)(A_BASE + arow * PITCH + (tid & 1) * 16);

    float acc[4][8][4];
    #pragma unroll
    for (int i = 0; i < 4; ++i)
        #pragma unroll
        for (int j = 0; j < 8; ++j)
            #pragma unroll
            for (int k = 0; k < 4; ++k) acc[i][j][k] = 0.f;

    float areg[8];                                    // fp32 A pipeline regs

    auto ldg_chunk = [&](int c) {
        const float4 v0 = *(const float4*)(axbase + c * BK);
        const float4 v1 = *(const float4*)(axbase + c * BK + 4);
        areg[0] = v0.x; areg[1] = v0.y; areg[2] = v0.z; areg[3] = v0.w;
        areg[4] = v1.x; areg[5] = v1.y; areg[6] = v1.z; areg[7] = v1.w;
    };
    auto sts_chunk = [&](int p) {                     // split + store to buf p
        uint32_t hp[4], mp[4];
        #pragma unroll
        for (int j = 0; j < 4; ++j) {
            const float f0 = areg[2 * j], f1 = areg[2 * j + 1];
            const __half h0 = __float2half_rn(f0), h1 = __float2half_rn(f1);
            const __half m0 = __float2half_rn(f0 - __half2float(h0));
            const __half m1 = __float2half_rn(f1 - __half2float(h1));
            hp[j] = hpack(h0, h1);
            mp[j] = hpack(m0, m1);
        }
        *(uint4*)(smem + asts + p * A_BUF_B)        = make_uint4(hp[0], hp[1], hp[2], hp[3]);
        *(uint4*)(smem + asts + p * A_BUF_B + A_T)  = make_uint4(mp[0], mp[1], mp[2], mp[3]);
    };
    // W stage fill: 1024 x 16B chunks (2 splits x 256 rows x 2 groups), 4/thread
    auto issue_w = [&](int c) {
        const int kt = c * BK;
        const uint32_t sdst = sbase + (uint32_t)((c & 3) * WSTAGE_B);
        #pragma unroll
        for (int i = 0; i < 4; ++i) {
            const int q     = i * 256 + tid;
            const int split = q >> 9;
            const int t     = q & 511;
            const int row   = t >> 1;
            const int cc    = t & 1;
            const __half* src = (split ? g_wm : g_wh) + (size_t)(n0 + row) * INP + kt + cc * 8;
            cp16(sdst + (uint32_t)(split * B_T + row * PITCH + cc * 16), src);
        }
        cp_commit();
    };

    // ---- prologue ----
    ldg_chunk(0);
    issue_w(0); issue_w(1); issue_w(2);
    sts_chunk(0);
    ldg_chunk(1);

    for (int c = 0; c < CHUNKS; ++c) {
        cp_wait2();
        __syncthreads();

        const uint32_t wst = sbase + (uint32_t)((c & 3) * WSTAGE_B);
        const uint32_t aB  = sbase + (uint32_t)(A_BASE + (c & 1) * A_BUF_B +
                                                warp_m * 64 * PITCH) + laneA;
        const uint32_t bB  = wst + (uint32_t)(warp_n * 64 * PITCH) + laneB;

        uint32_t afr[4][4], bfh[8][2], bfm[8][2];

        // B-hi + A-hi fragments first
        #pragma unroll
        for (int bp = 0; bp < 4; ++bp) {
            uint32_t r4[4];
            ldsm_x4(r4, bB + (uint32_t)(bp * 16 * PITCH));
            bfh[bp * 2 + 0][0] = r4[0]; bfh[bp * 2 + 0][1] = r4[1];
            bfh[bp * 2 + 1][0] = r4[2]; bfh[bp * 2 + 1][1] = r4[3];
        }
        #pragma unroll
        for (int mt = 0; mt < 4; ++mt)
            ldsm_x4(afr[mt], aB + (uint32_t)(mt * 16 * PITCH));

        // producers: next W stage, A split-store (c+1), A LDG (c+2)
        if (c + 3 < CHUNKS) issue_w(c + 3);
        else                cp_commit();
        if (c + 1 < CHUNKS) sts_chunk((c + 1) & 1);
        if (c + 2 < CHUNKS) ldg_chunk(c + 2);

        // hh
        #pragma unroll
        for (int mt = 0; mt < 4; ++mt)
            #pragma unroll
            for (int nt = 0; nt < 8; ++nt)
                mma_f16(acc[mt][nt], afr[mt], bfh[nt]);

        // B-mid under the hh MMAs' shadow, then hm
        #pragma unroll
        for (int bp = 0; bp < 4; ++bp) {
            uint32_t r4[4];
            ldsm_x4(r4, bB + (uint32_t)(B_T + bp * 16 * PITCH));
            bfm[bp * 2 + 0][0] = r4[0]; bfm[bp * 2 + 0][1] = r4[1];
            bfm[bp * 2 + 1][0] = r4[2]; bfm[bp * 2 + 1][1] = r4[3];
        }
        #pragma unroll
        for (int mt = 0; mt < 4; ++mt)
            #pragma unroll
            for (int nt = 0; nt < 8; ++nt)
                mma_f16(acc[mt][nt], afr[mt], bfm[nt]);

        // A-mid, then mh
        #pragma unroll
        for (int mt = 0; mt < 4; ++mt)
            ldsm_x4(afr[mt], aB + (uint32_t)(A_T + mt * 16 * PITCH));
        #pragma unroll
        for (int mt = 0; mt < 4; ++mt)
            #pragma unroll
            for (int nt = 0; nt < 8; ++nt)
                mma_f16(acc[mt][nt], afr[mt], bfh[nt]);
    }

    // ---- stage 2: acc -> smem xp tile (overlays all pipeline buffers) ----
    __syncthreads();
    float* xs = (float*)smem;              // [128][XP]
    const int tr = lid >> 2;
    const int tc = (lid & 3) * 2;
    #pragma unroll
    for (int nt = 0; nt < 8; ++nt) {
        const int col = warp_n * 64 + nt * 8 + tc;
        #pragma unroll
        for (int mt = 0; mt < 4; ++mt) {
            const int row = warp_m * 64 + mt * 16 + tr;
            *(float2*)&xs[row * XP + col]       = make_float2(acc[mt][nt][0], acc[mt][nt][1]);
            *(float2*)&xs[(row + 8) * XP + col] = make_float2(acc[mt][nt][2], acc[mt][nt][3]);
        }
    }
    __syncthreads();

    // ---- stage 3: LIF scan from smem (256 threads, one per h column) ----
    {
        const int h = n0 + tid;
        const float bias_h = bias[h];

        float v[4]  = {0.f, 0.f, 0.f, 0.f};
        float av[4] = {0.f, 0.f, 0.f, 0.f};

        float* po = out + (size_t)b * HID + h;

        #pragma unroll 1
        for (int t = 0; t < T_STEPS; t += 8) {
            float yin[8];
            #pragma unroll
            for (int u = 0; u < 8; ++u)
                yin[u] = xs[(t + u) * XP + tid] + bias_h;

            #pragma unroll
            for (int u = 0; u < 8; ++u) {
                float y  = yin[u];
                float sc = 0.f;
                #pragma unroll
                for (int l = 0; l < 4; ++l) {
                    const float cch = y * 0.5f;          // exact
                    float vv   = v[l];
                    float accv = 0.f, accs = 0.f;
                    #pragma unroll
                    for (int s = 0; s < 4; ++s) {
                        vv = __fmaf_rn(vv, 0.5f, cch);           // charge
                        const float sp = (vv >= 1.0f) ? 1.0f : 0.0f;
                        vv -= sp;                                 // soft reset
                        accv += vv;
                        accs += sp;
                    }
                    v[l]  = vv;
                    y     = accv * 0.25f;
                    av[l] = y;
                    sc    = accs * 0.25f;
                }
                po[(size_t)(t + u) * BH] = sc;
            }
        }

        #pragma unroll
        for (int l = 0; l < 4; ++l)
            states[(size_t)l * BH + (size_t)b * HID + h] = av[l];
    }
}

// ---------------------------------------------------------------------------
// Launch
// ---------------------------------------------------------------------------
extern "C" void kernel_launch(void* const* d_in, const int* in_sizes, int n_in,
                              void* d_out, int out_size)
{
    const float* x = (const float*)d_in[0];   // [T, B, INP]
    const float* W = (const float*)d_in[1];   // [HID, INP]
    const float* b = (const float*)d_in[2];   // [HID]

    float* out    = (float*)d_out;                    // [T, B, H]
    float* states = out + (size_t)T_STEPS * BH;       // [4, B, H]

    // 1) W split only (x is split in-kernel)
    split_w_kernel<<<W_SPLIT_BLOCKS, 256>>>((const float4*)W);

    // 2) fused GEMM + scan
    cudaFuncSetAttribute(fused_kernel,
                         cudaFuncAttributeMaxDynamicSharedMemorySize, SMEM_TOTAL);
    dim3 grid(HID / BN, BATCH);                       // (2, 512)
    fused_kernel<<<grid, 256, SMEM_TOTAL>>>(x, b, out, states);
}